// round 8
// baseline (speedup 1.0000x reference)
#include <cuda_runtime.h>

#define N_PTS 160000
#define C 64
#define SCALE_XY 2073600
#define PID_SPACE (2*SCALE_XY)            /* 4,147,200 pids */
#define WORDS (PID_SPACE/2)               /* 2,073,600 u32 words, 2 pids/word */

/* persistent-kernel geometry (K1, K3) */
#define NBLK 592                          /* 4 blocks/SM x 148 SMs */
#define NTHR 256
#define GSZ (NBLK*NTHR)                   /* 151,552 */

/* scan geometry (K2) */
#define SCAN_BLK 256
#define WPT 8
#define TILE_W (SCAN_BLK*WPT)             /* 2048 words */
#define NB1 ((WORDS + TILE_W - 1)/TILE_W) /* 1013 */
#define WORDS_PAD (NB1*TILE_W)

#define FLAG_AGG (1ULL << 62)
#define FLAG_PRE (2ULL << 62)
#define VAL_MASK ((1ULL << 50) - 1)

// ---------------- static scratch ----------------
__device__ unsigned int       g_zmask32[WORDS_PAD];
__device__ unsigned int       g_vbase[PID_SPACE];
__device__ int                g_pidlist[N_PTS];
__device__ int                g_head[N_PTS];
__device__ int                g_next[N_PTS];
__device__ unsigned char      g_zi[N_PTS];
__device__ unsigned long long g_state[NB1];
__device__ double             g_s[8];
__device__ double             g_m[36];
__device__ float              g_W2[512];
__device__ float              g_shift[C];
__device__ int                g_P;
__device__ int                g_barc;
__device__ volatile unsigned  g_barg;

__device__ __forceinline__ unsigned long long pack_ov(unsigned w) {
    unsigned occ = (unsigned)((w & 0xffffu) != 0u) + (unsigned)((w >> 16) != 0u);
    return ((unsigned long long)occ << 32) | (unsigned)__popc(w);
}
__device__ __forceinline__ unsigned long long vload(const unsigned long long* p) {
    return *(volatile const unsigned long long*)p;
}
__device__ __forceinline__ void vstore(unsigned long long* p, unsigned long long v) {
    *(volatile unsigned long long*)p = v;
}

// LIGHT grid barrier: fences only in thread 0 (cumulative via __syncthreads).
// Post-barrier cross-block data must be read via __ldcg / atomics (L2), which
// this file's phases do — so no per-thread L1 flush is needed.
__device__ __forceinline__ void gridbar() {
    __syncthreads();
    if (threadIdx.x == 0) {
        __threadfence();                          // release block's prior writes
        unsigned gen = g_barg;
        if (atomicAdd(&g_barc, 1) == NBLK - 1) {
            g_barc = 0;
            __threadfence();
            g_barg = gen + 1;
        } else {
            while (g_barg == gen) { }
            __threadfence();                      // acquire
        }
    }
    __syncthreads();
}

// ================= K1: zero scratch -> bar -> moments/zmask/zi =================
__global__ void __launch_bounds__(NTHR, 4)
k1_zero_stats(const float* __restrict__ pts, const int* __restrict__ pmc) {
    int t = threadIdx.x;
    int gtid = blockIdx.x * NTHR + t;
    int lane = t & 31;

    {   // P0: zero
        uint4 z4 = make_uint4(0u, 0u, 0u, 0u);
        uint4* zm = (uint4*)g_zmask32;
        for (int j = gtid; j < WORDS_PAD / 4; j += GSZ) zm[j] = z4;
        int4 m1 = make_int4(-1, -1, -1, -1);
        int4* hd = (int4*)g_head;
        for (int j = gtid; j < N_PTS / 4; j += GSZ) hd[j] = m1;
        for (int j = gtid; j < NB1; j += GSZ) g_state[j] = 0ULL;
        if (gtid < 8)       g_s[gtid] = 0.0;
        else if (gtid < 44) g_m[gtid - 8] = 0.0;
    }
    gridbar();

    {   // P1: stats (atomicOr executes at L2 -> sees zeroes via barrier's release)
        float s[8], m[36];
        #pragma unroll
        for (int k = 0; k < 8; k++) s[k] = 0.f;
        #pragma unroll
        for (int k = 0; k < 36; k++) m[k] = 0.f;
        for (int i = gtid; i < N_PTS; i += GSZ) {
            const float* p = pts + (size_t)i * 9;
            float x[8];
            #pragma unroll
            for (int k = 0; k < 8; k++) x[k] = p[1 + k];
            #pragma unroll
            for (int k = 0; k < 8; k++) {
                s[k] += x[k];
                #pragma unroll
                for (int l = 0; l <= k; l++) m[k * (k + 1) / 2 + l] += x[k] * x[l];
            }
            int zi = (int)x[5];                   // z in [0,16), voxel z size 1
            g_zi[i] = (unsigned char)zi;
            int pid = pmc[i];
            atomicOr(&g_zmask32[pid >> 1], (1u << zi) << ((pid & 1) * 16));
        }
        #pragma unroll
        for (int o = 16; o > 0; o >>= 1) {
            #pragma unroll
            for (int k = 0; k < 8; k++)  s[k] += __shfl_down_sync(0xffffffffu, s[k], o);
            #pragma unroll
            for (int k = 0; k < 36; k++) m[k] += __shfl_down_sync(0xffffffffu, m[k], o);
        }
        __shared__ double sd[44];
        if (t < 44) sd[t] = 0.0;
        __syncthreads();
        if (lane == 0) {
            for (int k = 0; k < 8;  k++) atomicAdd(&sd[k],     (double)s[k]);
            for (int k = 0; k < 36; k++) atomicAdd(&sd[8 + k], (double)m[k]);
        }
        __syncthreads();
        if (t < 8)       atomicAdd(&g_s[t],     sd[t]);
        else if (t < 44) atomicAdd(&g_m[t - 8], sd[t]);
    }
}

// ========== K2: single-pass scan + decoupled lookback + downsweep + BN =========
__global__ void k2_scan(const float* __restrict__ W,
                        const float* __restrict__ gamma,
                        const float* __restrict__ beta) {
    __shared__ unsigned long long s_warp[8];
    __shared__ unsigned long long s_agg;
    __shared__ unsigned long long s_exc;
    int t = threadIdx.x;
    int lane = t & 31, wid = t >> 5;
    int bid = blockIdx.x;

    size_t base = (size_t)bid * TILE_W + (size_t)t * WPT;
    uint4 a = *(const uint4*)&g_zmask32[base];
    uint4 b = *(const uint4*)&g_zmask32[base + 4];
    unsigned w[8] = {a.x, a.y, a.z, a.w, b.x, b.y, b.z, b.w};
    unsigned long long pre[8], run = 0ULL;
    #pragma unroll
    for (int k = 0; k < 8; k++) { pre[k] = run; run += pack_ov(w[k]); }

    unsigned long long inc = run;
    #pragma unroll
    for (int o = 1; o < 32; o <<= 1) {
        unsigned long long v = __shfl_up_sync(0xffffffffu, inc, o);
        if (lane >= o) inc += v;
    }
    if (lane == 31) s_warp[wid] = inc;
    __syncthreads();
    if (t < 8) {
        unsigned long long x = s_warp[t];
        unsigned long long sc = x;
        #pragma unroll
        for (int o = 1; o < 8; o <<= 1) {
            unsigned long long v = __shfl_up_sync(0xffu, sc, o);
            if (t >= o) sc += v;
        }
        s_warp[t] = sc - x;
        if (t == 7) s_agg = sc;
    }
    __syncthreads();

    if (wid == 0) {
        unsigned long long agg = s_agg;
        if (bid == 0) {
            if (lane == 0) { vstore(&g_state[0], FLAG_PRE | agg); s_exc = 0ULL; }
        } else {
            if (lane == 0) vstore(&g_state[bid], FLAG_AGG | agg);
            unsigned long long exc = 0ULL;
            int end = bid;
            while (end > 0) {
                int start = end - 32; if (start < 0) start = 0;
                int j = start + lane;
                bool active = (j < end);
                unsigned long long st = 0ULL;
                do {
                    if (active) st = vload(&g_state[j]);
                } while (__any_sync(0xffffffffu, active && (st >> 62) == 0ULL));
                unsigned pm = __ballot_sync(0xffffffffu, active && (st >> 62) == 2ULL);
                unsigned long long val = active ? (st & VAL_MASK) : 0ULL;
                if (pm) {
                    int hp = 31 - __clz(pm);
                    if (lane < hp) val = 0ULL;
                    #pragma unroll
                    for (int o = 16; o > 0; o >>= 1) val += __shfl_down_sync(0xffffffffu, val, o);
                    exc += val;
                    break;
                } else {
                    #pragma unroll
                    for (int o = 16; o > 0; o >>= 1) val += __shfl_down_sync(0xffffffffu, val, o);
                    exc += val;
                    end = start;
                }
            }
            if (lane == 0) {
                unsigned long long incl = exc + agg;
                vstore(&g_state[bid], FLAG_PRE | incl);
                s_exc = exc;
                if (bid == NB1 - 1) g_P = (int)(incl >> 32);
            }
        }
    }
    __syncthreads();

    unsigned long long e = s_exc + s_warp[wid] + (inc - run);
    #pragma unroll
    for (int k = 0; k < 8; k++) {
        unsigned ww = w[k];
        if (ww) {
            unsigned long long ee = e + pre[k];
            int pid0 = (int)((base + k) * 2);
            unsigned lo = ww & 0xffffu, hi = ww >> 16;
            if (lo) {
                g_vbase[pid0] = (unsigned)(ee & 0xffffffffu);
                g_pidlist[ee >> 32] = pid0;
                ee += (1ULL << 32) + (unsigned)__popc(lo);
            }
            if (hi) {
                g_vbase[pid0 + 1] = (unsigned)(ee & 0xffffffffu);
                g_pidlist[ee >> 32] = pid0 + 1;
            }
        }
    }

    if (bid == 0 && t >= 64 && t < 128) {     // BN fold overlaps others' lookback
        int c = t - 64;
        double wc[8];
        #pragma unroll
        for (int k = 0; k < 8; k++) wc[k] = (double)W[k * 64 + c];
        const double invn = 1.0 / (double)N_PTS;
        double mu = 0.0;
        #pragma unroll
        for (int k = 0; k < 8; k++) mu += g_s[k] * invn * wc[k];
        double e2 = 0.0;
        #pragma unroll
        for (int k = 0; k < 8; k++) {
            for (int l = 0; l < k; l++) e2 += 2.0 * g_m[k * (k + 1) / 2 + l] * invn * wc[k] * wc[l];
            e2 += g_m[k * (k + 1) / 2 + k] * invn * wc[k] * wc[k];
        }
        double var = e2 - mu * mu;
        double scale = (double)gamma[c] / sqrt(var + 1e-3);
        #pragma unroll
        for (int k = 0; k < 8; k++) g_W2[k * 64 + c] = (float)(wc[k] * scale);
        g_shift[c] = (float)((double)beta[c] - mu * scale);
    }
}

// ================= K3: link -> bar -> output =================
__global__ void __launch_bounds__(NTHR, 4)
k3_link_out(const float* __restrict__ pts, const float* __restrict__ sparse,
            const int* __restrict__ pmc, float* __restrict__ out) {
    int t = threadIdx.x, bid = blockIdx.x;
    int gtid = bid * NTHR + t;

    __shared__ float sW2[512];
    __shared__ float sSh[64];
    for (int j = t; j < 512; j += NTHR) sW2[j] = g_W2[j];
    if (t < 64) sSh[t] = g_shift[t];

    {   // P4: link (atomicExch at L2; <=2 points/thread at full-grid occupancy)
        int i0 = gtid;
        int pid0 = __ldg(&pmc[i0]);
        int zi0 = (int)g_zi[i0];
        bool v1 = (gtid + GSZ < N_PTS);
        int i1 = gtid + GSZ;
        int pid1 = v1 ? __ldg(&pmc[i1]) : 0;
        int zi1 = v1 ? (int)g_zi[i1] : 0;
        unsigned w0 = g_zmask32[pid0 >> 1];
        unsigned w1 = v1 ? g_zmask32[pid1 >> 1] : 0u;
        unsigned b0 = g_vbase[pid0];
        unsigned b1 = v1 ? g_vbase[pid1] : 0u;
        unsigned zm0 = (w0 >> ((pid0 & 1) * 16)) & 0xffffu;
        int slot0 = (int)b0 + __popc(zm0 & ((1u << zi0) - 1u));
        g_next[i0] = atomicExch(&g_head[slot0], i0);
        if (v1) {
            unsigned zm1 = (w1 >> ((pid1 & 1) * 16)) & 0xffffu;
            int slot1 = (int)b1 + __popc(zm1 & ((1u << zi1) - 1u));
            g_next[i1] = atomicExch(&g_head[slot1], i1);
        }
    }
    gridbar();

    {   // P5: output (head/next via __ldcg: written this kernel by other blocks)
        int g = t >> 4, l4 = t & 15;
        int P = g_P;
        for (int r = bid * 16 + g; r < N_PTS; r += NBLK * 16) {
            float4 sv = ((const float4*)sparse)[(size_t)r * 16 + l4];
            float4 res = sv;
            if (r < P) {
                int pid = g_pidlist[r];
                unsigned wz = g_zmask32[pid >> 1];
                unsigned zm = (wz >> ((pid & 1) * 16)) & 0xffffu;
                int nv = __popc(zm);
                if (nv >= 2) {
                    int base = (int)g_vbase[pid];
                    int c0 = l4 * 4;
                    float4 mx = make_float4(-3.4e38f, -3.4e38f, -3.4e38f, -3.4e38f);
                    for (int j = 0; j < nv; j++) {
                        int idx = __ldcg(&g_head[base + j]);
                        float a0 = 0.f, a1 = 0.f, a2 = 0.f, a3 = 0.f;
                        int cnt = 0;
                        while (idx >= 0) {
                            const float* p = pts + (size_t)idx * 9;
                            int nxt = __ldcg(&g_next[idx]);
                            float x[8];
                            #pragma unroll
                            for (int k = 0; k < 8; k++) x[k] = __ldg(&p[1 + k]);
                            float h0 = sSh[c0], h1 = sSh[c0 + 1], h2 = sSh[c0 + 2], h3 = sSh[c0 + 3];
                            #pragma unroll
                            for (int k = 0; k < 8; k++) {
                                h0 = fmaf(x[k], sW2[k * 64 + c0],     h0);
                                h1 = fmaf(x[k], sW2[k * 64 + c0 + 1], h1);
                                h2 = fmaf(x[k], sW2[k * 64 + c0 + 2], h2);
                                h3 = fmaf(x[k], sW2[k * 64 + c0 + 3], h3);
                            }
                            a0 += fmaxf(h0, 0.f); a1 += fmaxf(h1, 0.f);
                            a2 += fmaxf(h2, 0.f); a3 += fmaxf(h3, 0.f);
                            cnt++;
                            idx = nxt;
                        }
                        float ic = 1.0f / (float)cnt;
                        mx.x = fmaxf(mx.x, a0 * ic);
                        mx.y = fmaxf(mx.y, a1 * ic);
                        mx.z = fmaxf(mx.z, a2 * ic);
                        mx.w = fmaxf(mx.w, a3 * ic);
                    }
                    float4 cand = make_float4(sv.x + mx.x, sv.y + mx.y, sv.z + mx.z, sv.w + mx.w);
                    if (nv < 16) {
                        cand.x = fmaxf(cand.x, 0.f); cand.y = fmaxf(cand.y, 0.f);
                        cand.z = fmaxf(cand.z, 0.f); cand.w = fmaxf(cand.w, 0.f);
                    }
                    res = make_float4(sv.x + cand.x, sv.y + cand.y, sv.z + cand.z, sv.w + cand.w);
                }
            }
            ((float4*)out)[(size_t)r * 16 + l4] = res;
        }
    }
}

// ---------------- launch: 3 kernels ----------------
extern "C" void kernel_launch(void* const* d_in, const int* in_sizes, int n_in,
                              void* d_out, int out_size) {
    const float* pts    = (const float*)d_in[0];
    const float* sparse = (const float*)d_in[1];
    const float* W      = (const float*)d_in[2];
    const float* gamma  = (const float*)d_in[3];
    const float* beta   = (const float*)d_in[4];
    const int*   pmc    = (const int*)d_in[5];
    float* out = (float*)d_out;

    k1_zero_stats<<<NBLK, NTHR>>>(pts, pmc);
    k2_scan      <<<NB1, SCAN_BLK>>>(W, gamma, beta);
    k3_link_out  <<<NBLK, NTHR>>>(pts, sparse, pmc, out);
}

// round 9
// speedup vs baseline: 1.5412x; 1.5412x over previous
#include <cuda_runtime.h>

#define N_PTS 160000
#define C 64
#define SCALE_XY 2073600
/* x,y < 480 (48m / 0.1m): used pids are [0,690240) u [SCALE_XY, SCALE_XY+690240).
   cid = pid - (pid>=SCALE_XY)*1383360 is order-preserving over used pids. */
#define HALF_CID 690240
#define BSHIFT (SCALE_XY - HALF_CID)        /* 1,383,360 */
#define CID_SPACE (2*HALF_CID)              /* 1,380,480 */
#define WORDS (CID_SPACE/2)                 /* 690,240 u32 words, 2 cids/word */
#define SCAN_BLK 256
#define WPT 8
#define TILE_W (SCAN_BLK*WPT)               /* 2048 words */
#define NB1 ((WORDS + TILE_W - 1)/TILE_W)   /* 338 */
#define WORDS_PAD (NB1*TILE_W)              /* 692,224 */

#define FLAG_AGG (1ULL << 62)
#define FLAG_PRE (2ULL << 62)
#define VAL_MASK ((1ULL << 50) - 1)

// ---------------- static scratch ----------------
__device__ unsigned int       g_zmask32[WORDS_PAD];  // 2 cids/word, 16 z-bits each
__device__ unsigned int       g_vbase[CID_SPACE];    // written ONLY at occupied cids
__device__ int                g_pidlist[N_PTS];      // pillar rank -> cid
__device__ int                g_head[N_PTS];         // per-voxel point-list head (-1)
__device__ int                g_next[N_PTS];         // per-point list link
__device__ unsigned char      g_zi[N_PTS];           // per-point z bin
__device__ unsigned long long g_state[NB1];          // decoupled-lookback tile state
__device__ double             g_s[8];
__device__ double             g_m[36];
__device__ float              g_W2[512];             // W * BN scale (folded)
__device__ float              g_shift[C];
__device__ int                g_P;

__device__ __forceinline__ int to_cid(int pid) {
    return pid - (pid >= SCALE_XY ? BSHIFT : 0);
}
__device__ __forceinline__ unsigned long long pack_ov(unsigned w) {
    unsigned occ = (unsigned)((w & 0xffffu) != 0u) + (unsigned)((w >> 16) != 0u);
    return ((unsigned long long)occ << 32) | (unsigned)__popc(w);
}
__device__ __forceinline__ unsigned long long vload(const unsigned long long* p) {
    return *(volatile const unsigned long long*)p;
}
__device__ __forceinline__ void vstore(unsigned long long* p, unsigned long long v) {
    *(volatile unsigned long long*)p = v;
}

// ---------------- zero scratch (~3.5 MB) ----------------
__global__ void kzero() {
    size_t i = (size_t)blockIdx.x * blockDim.x + threadIdx.x;
    size_t stride = (size_t)gridDim.x * blockDim.x;
    uint4 z4 = make_uint4(0u, 0u, 0u, 0u);
    uint4* zm = (uint4*)g_zmask32;
    for (size_t j = i; j < WORDS_PAD / 4; j += stride) zm[j] = z4;
    int4 m1 = make_int4(-1, -1, -1, -1);
    int4* hd = (int4*)g_head;
    for (size_t j = i; j < N_PTS / 4; j += stride) hd[j] = m1;
    if (i < NB1) g_state[i] = 0ULL;
    if (i < 8)  g_s[i] = 0.0;
    if (i < 36) g_m[i] = 0.0;
}

// -------- moments + zmask + z side-channel (148 blocks: cheap epilogue) -------
__global__ void k_stats(const float* __restrict__ pts, const int* __restrict__ pmc) {
    float s[8]; float m[36];
    #pragma unroll
    for (int k = 0; k < 8; k++) s[k] = 0.f;
    #pragma unroll
    for (int k = 0; k < 36; k++) m[k] = 0.f;

    int tid = blockIdx.x * blockDim.x + threadIdx.x;
    int stride = gridDim.x * blockDim.x;
    for (int i = tid; i < N_PTS; i += stride) {
        const float* p = pts + (size_t)i * 9;
        float x[8];
        #pragma unroll
        for (int k = 0; k < 8; k++) x[k] = p[1 + k];
        #pragma unroll
        for (int k = 0; k < 8; k++) {
            s[k] += x[k];
            #pragma unroll
            for (int l = 0; l <= k; l++) m[k * (k + 1) / 2 + l] += x[k] * x[l];
        }
        int zi = (int)x[5];                 // z in [0,16), voxel z size 1
        g_zi[i] = (unsigned char)zi;
        int cid = to_cid(pmc[i]);
        atomicOr(&g_zmask32[cid >> 1], (1u << zi) << ((cid & 1) * 16));
    }
    #pragma unroll
    for (int o = 16; o > 0; o >>= 1) {
        #pragma unroll
        for (int k = 0; k < 8; k++)  s[k] += __shfl_down_sync(0xffffffffu, s[k], o);
        #pragma unroll
        for (int k = 0; k < 36; k++) m[k] += __shfl_down_sync(0xffffffffu, m[k], o);
    }
    __shared__ double sd[44];
    if (threadIdx.x < 44) sd[threadIdx.x] = 0.0;
    __syncthreads();
    if ((threadIdx.x & 31) == 0) {
        for (int k = 0; k < 8;  k++) atomicAdd(&sd[k],     (double)s[k]);
        for (int k = 0; k < 36; k++) atomicAdd(&sd[8 + k], (double)m[k]);
    }
    __syncthreads();
    if (threadIdx.x < 8)                      atomicAdd(&g_s[threadIdx.x],     sd[threadIdx.x]);
    if (threadIdx.x >= 8 && threadIdx.x < 44) atomicAdd(&g_m[threadIdx.x - 8], sd[threadIdx.x]);
}

// -------- single-pass scan + decoupled lookback + downsweep + BN fold ---------
__global__ void k_scan(const float* __restrict__ W,
                       const float* __restrict__ gamma,
                       const float* __restrict__ beta) {
    __shared__ unsigned long long s_warp[8];
    __shared__ unsigned long long s_agg;
    __shared__ unsigned long long s_exc;
    int t = threadIdx.x;
    int lane = t & 31, wid = t >> 5;
    int bid = blockIdx.x;

    size_t base = (size_t)bid * TILE_W + (size_t)t * WPT;
    uint4 a = *(const uint4*)&g_zmask32[base];
    uint4 b = *(const uint4*)&g_zmask32[base + 4];
    unsigned w[8] = {a.x, a.y, a.z, a.w, b.x, b.y, b.z, b.w};
    unsigned long long pre[8], run = 0ULL;
    #pragma unroll
    for (int k = 0; k < 8; k++) { pre[k] = run; run += pack_ov(w[k]); }

    unsigned long long inc = run;
    #pragma unroll
    for (int o = 1; o < 32; o <<= 1) {
        unsigned long long v = __shfl_up_sync(0xffffffffu, inc, o);
        if (lane >= o) inc += v;
    }
    if (lane == 31) s_warp[wid] = inc;
    __syncthreads();
    if (t < 8) {
        unsigned long long x = s_warp[t];
        unsigned long long sc = x;
        #pragma unroll
        for (int o = 1; o < 8; o <<= 1) {
            unsigned long long v = __shfl_up_sync(0xffu, sc, o);
            if (t >= o) sc += v;
        }
        s_warp[t] = sc - x;
        if (t == 7) s_agg = sc;
    }
    __syncthreads();

    if (wid == 0) {
        unsigned long long agg = s_agg;
        if (bid == 0) {
            if (lane == 0) { vstore(&g_state[0], FLAG_PRE | agg); s_exc = 0ULL; }
        } else {
            if (lane == 0) vstore(&g_state[bid], FLAG_AGG | agg);
            unsigned long long exc = 0ULL;
            int end = bid;
            while (end > 0) {
                int start = end - 32; if (start < 0) start = 0;
                int j = start + lane;
                bool active = (j < end);
                unsigned long long st = 0ULL;
                do {
                    if (active) st = vload(&g_state[j]);
                } while (__any_sync(0xffffffffu, active && (st >> 62) == 0ULL));
                unsigned pm = __ballot_sync(0xffffffffu, active && (st >> 62) == 2ULL);
                unsigned long long val = active ? (st & VAL_MASK) : 0ULL;
                if (pm) {
                    int hp = 31 - __clz(pm);
                    if (lane < hp) val = 0ULL;
                    #pragma unroll
                    for (int o = 16; o > 0; o >>= 1) val += __shfl_down_sync(0xffffffffu, val, o);
                    exc += val;
                    break;
                } else {
                    #pragma unroll
                    for (int o = 16; o > 0; o >>= 1) val += __shfl_down_sync(0xffffffffu, val, o);
                    exc += val;
                    end = start;
                }
            }
            if (lane == 0) {
                unsigned long long incl = exc + agg;
                vstore(&g_state[bid], FLAG_PRE | incl);
                s_exc = exc;
                if (bid == NB1 - 1) g_P = (int)(incl >> 32);
            }
        }
    }
    __syncthreads();

    unsigned long long e = s_exc + s_warp[wid] + (inc - run);
    #pragma unroll
    for (int k = 0; k < 8; k++) {
        unsigned ww = w[k];
        if (ww) {
            unsigned long long ee = e + pre[k];
            int cid0 = (int)((base + k) * 2);
            unsigned lo = ww & 0xffffu, hi = ww >> 16;
            if (lo) {
                g_vbase[cid0] = (unsigned)(ee & 0xffffffffu);
                g_pidlist[ee >> 32] = cid0;
                ee += (1ULL << 32) + (unsigned)__popc(lo);
            }
            if (hi) {
                g_vbase[cid0 + 1] = (unsigned)(ee & 0xffffffffu);
                g_pidlist[ee >> 32] = cid0 + 1;
            }
        }
    }

    // BN fold — block 0 (no lookback wait); overlaps other blocks' lookback
    if (bid == 0 && t >= 64 && t < 128) {
        int c = t - 64;
        double wc[8];
        #pragma unroll
        for (int k = 0; k < 8; k++) wc[k] = (double)W[k * 64 + c];
        const double invn = 1.0 / (double)N_PTS;
        double mu = 0.0;
        #pragma unroll
        for (int k = 0; k < 8; k++) mu += g_s[k] * invn * wc[k];
        double e2 = 0.0;
        #pragma unroll
        for (int k = 0; k < 8; k++) {
            for (int l = 0; l < k; l++) e2 += 2.0 * g_m[k * (k + 1) / 2 + l] * invn * wc[k] * wc[l];
            e2 += g_m[k * (k + 1) / 2 + k] * invn * wc[k] * wc[k];
        }
        double var = e2 - mu * mu;
        double scale = (double)gamma[c] / sqrt(var + 1e-3);
        #pragma unroll
        for (int k = 0; k < 8; k++) g_W2[k * 64 + c] = (float)(wc[k] * scale);
        g_shift[c] = (float)((double)beta[c] - mu * scale);
    }
}

// -------- per-voxel point linked lists: 1 pt/thread, max warp parallelism -----
__global__ void k_link(const int* __restrict__ pmc) {
    int i = blockIdx.x * blockDim.x + threadIdx.x;   // grid covers N_PTS exactly
    int cid = to_cid(__ldg(&pmc[i]));
    int zi = (int)g_zi[i];
    unsigned w = g_zmask32[cid >> 1];
    unsigned vb = g_vbase[cid];
    unsigned zm = (w >> ((cid & 1) * 16)) & 0xffffu;
    int slot = (int)vb + __popc(zm & ((1u << zi) - 1u));
    g_next[i] = atomicExch(&g_head[slot], i);
}

// ------ output: traverse pillar's voxel chains, inline matmul+BN+ReLU ---------
__global__ void k_out(float* __restrict__ out,
                      const float* __restrict__ sparse,
                      const float* __restrict__ pts) {
    __shared__ float sW2[512];
    __shared__ float sSh[64];
    int t = threadIdx.x;
    for (int j = t; j < 512; j += 256) sW2[j] = g_W2[j];
    if (t < 64) sSh[t] = g_shift[t];
    __syncthreads();
    int g = t >> 4, lane = t & 15;
    int r = blockIdx.x * 16 + g;
    float4 sv = ((const float4*)sparse)[(size_t)r * 16 + lane];
    float4 res = sv;
    if (r < g_P) {
        int cid = g_pidlist[r];
        unsigned w = g_zmask32[cid >> 1];
        unsigned zm = (w >> ((cid & 1) * 16)) & 0xffffu;
        int nv = __popc(zm);
        if (nv >= 2) {                      // occupied: >=2 voxels in pillar
            int base = (int)g_vbase[cid];
            int c0 = lane * 4;
            float4 mx = make_float4(-3.4e38f, -3.4e38f, -3.4e38f, -3.4e38f);
            for (int j = 0; j < nv; j++) {
                int idx = g_head[base + j];
                float a0 = 0.f, a1 = 0.f, a2 = 0.f, a3 = 0.f;
                int cnt = 0;
                while (idx >= 0) {
                    const float* p = pts + (size_t)idx * 9;
                    int nxt = g_next[idx];
                    float x[8];
                    #pragma unroll
                    for (int k = 0; k < 8; k++) x[k] = __ldg(&p[1 + k]);
                    float h0 = sSh[c0], h1 = sSh[c0 + 1], h2 = sSh[c0 + 2], h3 = sSh[c0 + 3];
                    #pragma unroll
                    for (int k = 0; k < 8; k++) {
                        h0 = fmaf(x[k], sW2[k * 64 + c0],     h0);
                        h1 = fmaf(x[k], sW2[k * 64 + c0 + 1], h1);
                        h2 = fmaf(x[k], sW2[k * 64 + c0 + 2], h2);
                        h3 = fmaf(x[k], sW2[k * 64 + c0 + 3], h3);
                    }
                    a0 += fmaxf(h0, 0.f); a1 += fmaxf(h1, 0.f);
                    a2 += fmaxf(h2, 0.f); a3 += fmaxf(h3, 0.f);
                    cnt++;
                    idx = nxt;
                }
                float ic = 1.0f / (float)cnt;
                mx.x = fmaxf(mx.x, a0 * ic);
                mx.y = fmaxf(mx.y, a1 * ic);
                mx.z = fmaxf(mx.z, a2 * ic);
                mx.w = fmaxf(mx.w, a3 * ic);
            }
            float4 cand = make_float4(sv.x + mx.x, sv.y + mx.y, sv.z + mx.z, sv.w + mx.w);
            if (nv < 16) {
                cand.x = fmaxf(cand.x, 0.f); cand.y = fmaxf(cand.y, 0.f);
                cand.z = fmaxf(cand.z, 0.f); cand.w = fmaxf(cand.w, 0.f);
            }
            res = make_float4(sv.x + cand.x, sv.y + cand.y, sv.z + cand.z, sv.w + cand.w);
        }
    }
    ((float4*)out)[(size_t)r * 16 + lane] = res;
}

// ---------------- launch ----------------
extern "C" void kernel_launch(void* const* d_in, const int* in_sizes, int n_in,
                              void* d_out, int out_size) {
    const float* pts    = (const float*)d_in[0];  // [N,9]
    const float* sparse = (const float*)d_in[1];  // [N,64]
    const float* W      = (const float*)d_in[2];  // [8,64]
    const float* gamma  = (const float*)d_in[3];  // [64]
    const float* beta   = (const float*)d_in[4];  // [64]
    const int*   pmc    = (const int*)d_in[5];    // [N]
    float* out = (float*)d_out;

    kzero  <<<592, 256>>>();
    k_stats<<<148, 256>>>(pts, pmc);
    k_scan <<<NB1, SCAN_BLK>>>(W, gamma, beta);
    k_link <<<N_PTS / 256, 256>>>(pmc);
    k_out  <<<N_PTS / 16, 256>>>(out, sparse, pts);
}

// round 10
// speedup vs baseline: 1.6027x; 1.0398x over previous
#include <cuda_runtime.h>

#define N_PTS 160000
#define C 64
#define SCALE_XY 2073600
/* x,y < 480 (48m / 0.1m): used pids are [0,690240) u [SCALE_XY, SCALE_XY+690240).
   cid = pid - (pid>=SCALE_XY)*1383360 is order-preserving over used pids. */
#define HALF_CID 690240
#define BSHIFT (SCALE_XY - HALF_CID)        /* 1,383,360 */
#define CID_SPACE (2*HALF_CID)              /* 1,380,480 */
#define WORDS (CID_SPACE/2)                 /* 690,240 u32 words, 2 cids/word */
#define SCAN_BLK 256
#define WPT 8
#define TILE_W (SCAN_BLK*WPT)               /* 2048 words */
#define NB1 ((WORDS + TILE_W - 1)/TILE_W)   /* 338 */
#define WORDS_PAD (NB1*TILE_W)              /* 692,224 */

#define FLAG_AGG (1ULL << 62)
#define FLAG_PRE (2ULL << 62)
#define VAL_MASK ((1ULL << 50) - 1)

// ---------------- static scratch ----------------
__device__ unsigned int       g_zmask32[WORDS_PAD];  // 2 cids/word, 16 z-bits each
__device__ unsigned long long g_info[CID_SPACE];     // (vbase<<16)|zmask, occupied cids only
__device__ unsigned long long g_pinfo[N_PTS];        // rank -> (vbase<<16)|zmask
__device__ int                g_head[N_PTS];         // per-voxel point-list head (-1)
__device__ int                g_next[N_PTS];         // per-point list link
__device__ unsigned char      g_zi[N_PTS];           // per-point z bin
__device__ unsigned long long g_state[NB1];          // decoupled-lookback tile state
__device__ double             g_s[8];
__device__ double             g_m[36];
__device__ float              g_W2[512];             // W * BN scale (folded)
__device__ float              g_shift[C];
__device__ int                g_P;

__device__ __forceinline__ int to_cid(int pid) {
    return pid - (pid >= SCALE_XY ? BSHIFT : 0);
}
__device__ __forceinline__ unsigned long long pack_ov(unsigned w) {
    unsigned occ = (unsigned)((w & 0xffffu) != 0u) + (unsigned)((w >> 16) != 0u);
    return ((unsigned long long)occ << 32) | (unsigned)__popc(w);
}
__device__ __forceinline__ unsigned long long vload(const unsigned long long* p) {
    return *(volatile const unsigned long long*)p;
}
__device__ __forceinline__ void vstore(unsigned long long* p, unsigned long long v) {
    *(volatile unsigned long long*)p = v;
}

// ---------------- zero scratch (zmask + state only, ~2.8 MB) ----------------
__global__ void kzero() {
    size_t i = (size_t)blockIdx.x * blockDim.x + threadIdx.x;
    size_t stride = (size_t)gridDim.x * blockDim.x;
    uint4 z4 = make_uint4(0u, 0u, 0u, 0u);
    uint4* zm = (uint4*)g_zmask32;
    for (size_t j = i; j < WORDS_PAD / 4; j += stride) zm[j] = z4;
    if (i < NB1) g_state[i] = 0ULL;
    if (i < 8)  g_s[i] = 0.0;
    if (i < 36) g_m[i] = 0.0;
}

// -------- moments + zmask + z side-channel --------
__global__ void k_stats(const float* __restrict__ pts, const int* __restrict__ pmc) {
    float s[8]; float m[36];
    #pragma unroll
    for (int k = 0; k < 8; k++) s[k] = 0.f;
    #pragma unroll
    for (int k = 0; k < 36; k++) m[k] = 0.f;

    int tid = blockIdx.x * blockDim.x + threadIdx.x;
    int stride = gridDim.x * blockDim.x;
    for (int i = tid; i < N_PTS; i += stride) {
        const float* p = pts + (size_t)i * 9;
        float x[8];
        #pragma unroll
        for (int k = 0; k < 8; k++) x[k] = p[1 + k];
        #pragma unroll
        for (int k = 0; k < 8; k++) {
            s[k] += x[k];
            #pragma unroll
            for (int l = 0; l <= k; l++) m[k * (k + 1) / 2 + l] += x[k] * x[l];
        }
        int zi = (int)x[5];                 // z in [0,16), voxel z size 1
        g_zi[i] = (unsigned char)zi;
        int cid = to_cid(pmc[i]);
        atomicOr(&g_zmask32[cid >> 1], (1u << zi) << ((cid & 1) * 16));
    }
    #pragma unroll
    for (int o = 16; o > 0; o >>= 1) {
        #pragma unroll
        for (int k = 0; k < 8; k++)  s[k] += __shfl_down_sync(0xffffffffu, s[k], o);
        #pragma unroll
        for (int k = 0; k < 36; k++) m[k] += __shfl_down_sync(0xffffffffu, m[k], o);
    }
    __shared__ double sd[44];
    if (threadIdx.x < 44) sd[threadIdx.x] = 0.0;
    __syncthreads();
    if ((threadIdx.x & 31) == 0) {
        for (int k = 0; k < 8;  k++) atomicAdd(&sd[k],     (double)s[k]);
        for (int k = 0; k < 36; k++) atomicAdd(&sd[8 + k], (double)m[k]);
    }
    __syncthreads();
    if (threadIdx.x < 8)                      atomicAdd(&g_s[threadIdx.x],     sd[threadIdx.x]);
    if (threadIdx.x >= 8 && threadIdx.x < 44) atomicAdd(&g_m[threadIdx.x - 8], sd[threadIdx.x]);
}

// -------- single-pass scan + lookback + downsweep(packed info) + BN + head-fill
__global__ void k_scan(const float* __restrict__ W,
                       const float* __restrict__ gamma,
                       const float* __restrict__ beta) {
    __shared__ unsigned long long s_warp[8];
    __shared__ unsigned long long s_agg;
    __shared__ unsigned long long s_exc;
    int t = threadIdx.x;
    int lane = t & 31, wid = t >> 5;
    int bid = blockIdx.x;

    // head fill (-1), spread over scan blocks, coalesced, independent of scan
    {
        int per = (N_PTS / 4 + NB1 - 1) / NB1;           // int4 units per block
        int j0 = bid * per + t;
        int j1 = min((bid + 1) * per, N_PTS / 4);
        int4 m1 = make_int4(-1, -1, -1, -1);
        for (int j = j0; j < j1; j += SCAN_BLK) ((int4*)g_head)[j] = m1;
    }

    size_t base = (size_t)bid * TILE_W + (size_t)t * WPT;
    uint4 a = *(const uint4*)&g_zmask32[base];
    uint4 b = *(const uint4*)&g_zmask32[base + 4];
    unsigned w[8] = {a.x, a.y, a.z, a.w, b.x, b.y, b.z, b.w};
    unsigned long long pre[8], run = 0ULL;
    #pragma unroll
    for (int k = 0; k < 8; k++) { pre[k] = run; run += pack_ov(w[k]); }

    unsigned long long inc = run;
    #pragma unroll
    for (int o = 1; o < 32; o <<= 1) {
        unsigned long long v = __shfl_up_sync(0xffffffffu, inc, o);
        if (lane >= o) inc += v;
    }
    if (lane == 31) s_warp[wid] = inc;
    __syncthreads();
    if (t < 8) {
        unsigned long long x = s_warp[t];
        unsigned long long sc = x;
        #pragma unroll
        for (int o = 1; o < 8; o <<= 1) {
            unsigned long long v = __shfl_up_sync(0xffu, sc, o);
            if (t >= o) sc += v;
        }
        s_warp[t] = sc - x;
        if (t == 7) s_agg = sc;
    }
    __syncthreads();

    if (wid == 0) {
        unsigned long long agg = s_agg;
        if (bid == 0) {
            if (lane == 0) { vstore(&g_state[0], FLAG_PRE | agg); s_exc = 0ULL; }
        } else {
            if (lane == 0) vstore(&g_state[bid], FLAG_AGG | agg);
            unsigned long long exc = 0ULL;
            int end = bid;
            while (end > 0) {
                int start = end - 32; if (start < 0) start = 0;
                int j = start + lane;
                bool active = (j < end);
                unsigned long long st = 0ULL;
                do {
                    if (active) st = vload(&g_state[j]);
                } while (__any_sync(0xffffffffu, active && (st >> 62) == 0ULL));
                unsigned pm = __ballot_sync(0xffffffffu, active && (st >> 62) == 2ULL);
                unsigned long long val = active ? (st & VAL_MASK) : 0ULL;
                if (pm) {
                    int hp = 31 - __clz(pm);
                    if (lane < hp) val = 0ULL;
                    #pragma unroll
                    for (int o = 16; o > 0; o >>= 1) val += __shfl_down_sync(0xffffffffu, val, o);
                    exc += val;
                    break;
                } else {
                    #pragma unroll
                    for (int o = 16; o > 0; o >>= 1) val += __shfl_down_sync(0xffffffffu, val, o);
                    exc += val;
                    end = start;
                }
            }
            if (lane == 0) {
                unsigned long long incl = exc + agg;
                vstore(&g_state[bid], FLAG_PRE | incl);
                s_exc = exc;
                if (bid == NB1 - 1) g_P = (int)(incl >> 32);
            }
        }
    }
    __syncthreads();

    unsigned long long e = s_exc + s_warp[wid] + (inc - run);
    #pragma unroll
    for (int k = 0; k < 8; k++) {
        unsigned ww = w[k];
        if (ww) {
            unsigned long long ee = e + pre[k];
            int cid0 = (int)((base + k) * 2);
            unsigned lo = ww & 0xffffu, hi = ww >> 16;
            if (lo) {
                unsigned long long info = ((ee & 0xffffffffULL) << 16) | lo;
                g_info[cid0] = info;
                g_pinfo[ee >> 32] = info;
                ee += (1ULL << 32) + (unsigned)__popc(lo);
            }
            if (hi) {
                unsigned long long info = ((ee & 0xffffffffULL) << 16) | hi;
                g_info[cid0 + 1] = info;
                g_pinfo[ee >> 32] = info;
            }
        }
    }

    // BN fold — block 0 (no lookback wait); overlaps other blocks' lookback
    if (bid == 0 && t >= 64 && t < 128) {
        int c = t - 64;
        double wc[8];
        #pragma unroll
        for (int k = 0; k < 8; k++) wc[k] = (double)W[k * 64 + c];
        const double invn = 1.0 / (double)N_PTS;
        double mu = 0.0;
        #pragma unroll
        for (int k = 0; k < 8; k++) mu += g_s[k] * invn * wc[k];
        double e2 = 0.0;
        #pragma unroll
        for (int k = 0; k < 8; k++) {
            for (int l = 0; l < k; l++) e2 += 2.0 * g_m[k * (k + 1) / 2 + l] * invn * wc[k] * wc[l];
            e2 += g_m[k * (k + 1) / 2 + k] * invn * wc[k] * wc[k];
        }
        double var = e2 - mu * mu;
        double scale = (double)gamma[c] / sqrt(var + 1e-3);
        #pragma unroll
        for (int k = 0; k < 8; k++) g_W2[k * 64 + c] = (float)(wc[k] * scale);
        g_shift[c] = (float)((double)beta[c] - mu * scale);
    }
}

// -------- per-voxel point linked lists: ONE scattered load per point ----------
__global__ void k_link(const int* __restrict__ pmc) {
    int i = blockIdx.x * blockDim.x + threadIdx.x;   // grid covers N_PTS exactly
    int cid = to_cid(__ldg(&pmc[i]));
    int zi = (int)g_zi[i];
    unsigned long long info = g_info[cid];           // (vbase<<16)|zmask, one sector
    unsigned zm = (unsigned)(info & 0xffffu);
    int slot = (int)(info >> 16) + __popc(zm & ((1u << zi) - 1u));
    g_next[i] = atomicExch(&g_head[slot], i);
}

// ------ output: coalesced pinfo, traverse voxel chains, inline matmul+BN+ReLU -
__global__ void k_out(float* __restrict__ out,
                      const float* __restrict__ sparse,
                      const float* __restrict__ pts) {
    __shared__ float sW2[512];
    __shared__ float sSh[64];
    int t = threadIdx.x;
    for (int j = t; j < 512; j += 256) sW2[j] = g_W2[j];
    if (t < 64) sSh[t] = g_shift[t];
    __syncthreads();
    int g = t >> 4, lane = t & 15;
    int r = blockIdx.x * 16 + g;
    float4 sv = ((const float4*)sparse)[(size_t)r * 16 + lane];
    float4 res = sv;
    if (r < g_P) {
        unsigned long long info = g_pinfo[r];        // coalesced u64
        unsigned zm = (unsigned)(info & 0xffffu);
        int nv = __popc(zm);
        if (nv >= 2) {                      // occupied: >=2 voxels in pillar
            int base = (int)(info >> 16);
            int c0 = lane * 4;
            float4 mx = make_float4(-3.4e38f, -3.4e38f, -3.4e38f, -3.4e38f);
            for (int j = 0; j < nv; j++) {
                int idx = g_head[base + j];
                float a0 = 0.f, a1 = 0.f, a2 = 0.f, a3 = 0.f;
                int cnt = 0;
                while (idx >= 0) {
                    const float* p = pts + (size_t)idx * 9;
                    int nxt = g_next[idx];
                    float x[8];
                    #pragma unroll
                    for (int k = 0; k < 8; k++) x[k] = __ldg(&p[1 + k]);
                    float h0 = sSh[c0], h1 = sSh[c0 + 1], h2 = sSh[c0 + 2], h3 = sSh[c0 + 3];
                    #pragma unroll
                    for (int k = 0; k < 8; k++) {
                        h0 = fmaf(x[k], sW2[k * 64 + c0],     h0);
                        h1 = fmaf(x[k], sW2[k * 64 + c0 + 1], h1);
                        h2 = fmaf(x[k], sW2[k * 64 + c0 + 2], h2);
                        h3 = fmaf(x[k], sW2[k * 64 + c0 + 3], h3);
                    }
                    a0 += fmaxf(h0, 0.f); a1 += fmaxf(h1, 0.f);
                    a2 += fmaxf(h2, 0.f); a3 += fmaxf(h3, 0.f);
                    cnt++;
                    idx = nxt;
                }
                float ic = 1.0f / (float)cnt;
                mx.x = fmaxf(mx.x, a0 * ic);
                mx.y = fmaxf(mx.y, a1 * ic);
                mx.z = fmaxf(mx.z, a2 * ic);
                mx.w = fmaxf(mx.w, a3 * ic);
            }
            float4 cand = make_float4(sv.x + mx.x, sv.y + mx.y, sv.z + mx.z, sv.w + mx.w);
            if (nv < 16) {
                cand.x = fmaxf(cand.x, 0.f); cand.y = fmaxf(cand.y, 0.f);
                cand.z = fmaxf(cand.z, 0.f); cand.w = fmaxf(cand.w, 0.f);
            }
            res = make_float4(sv.x + cand.x, sv.y + cand.y, sv.z + cand.z, sv.w + cand.w);
        }
    }
    ((float4*)out)[(size_t)r * 16 + lane] = res;
}

// ---------------- launch ----------------
extern "C" void kernel_launch(void* const* d_in, const int* in_sizes, int n_in,
                              void* d_out, int out_size) {
    const float* pts    = (const float*)d_in[0];  // [N,9]
    const float* sparse = (const float*)d_in[1];  // [N,64]
    const float* W      = (const float*)d_in[2];  // [8,64]
    const float* gamma  = (const float*)d_in[3];  // [64]
    const float* beta   = (const float*)d_in[4];  // [64]
    const int*   pmc    = (const int*)d_in[5];    // [N]
    float* out = (float*)d_out;

    kzero  <<<592, 256>>>();
    k_stats<<<148, 256>>>(pts, pmc);
    k_scan <<<NB1, SCAN_BLK>>>(W, gamma, beta);
    k_link <<<N_PTS / 256, 256>>>(pmc);
    k_out  <<<N_PTS / 16, 256>>>(out, sparse, pts);
}